// round 1
// baseline (speedup 1.0000x reference)
#include <cuda_runtime.h>
#include <cuda_bf16.h>
#include <math.h>

// Problem constants
#define BB   2
#define TT   2048
#define BT   4096      // B*T
#define DIMC 1024
#define NH   16
#define HD   64
#define HID  4096
#define EPSV 1e-6f

// ---------------- scratch (device globals; no allocation allowed) ----------
__device__ float g_xn[BT * DIMC];
__device__ float g_q [BT * DIMC];
__device__ float g_k [BT * DIMC];
__device__ float g_v [BT * DIMC];
__device__ float g_ao[BT * DIMC];
__device__ float g_x1[BT * DIMC];
__device__ float g_h [BT * HID];

// ---------------- RMSNorm ---------------------------------------------------
// one block per row, 256 threads, 4 elements/thread (DIM=1024)
__global__ void rmsnorm_kernel(const float* __restrict__ x,
                               const float* __restrict__ g,
                               float* __restrict__ y) {
    int row = blockIdx.x;
    int tid = threadIdx.x;
    const float* xr = x + (size_t)row * DIMC;
    float4 xv = *(const float4*)(xr + tid * 4);
    float s = xv.x * xv.x + xv.y * xv.y + xv.z * xv.z + xv.w * xv.w;
    #pragma unroll
    for (int off = 16; off; off >>= 1) s += __shfl_xor_sync(0xFFFFFFFFu, s, off);
    __shared__ float ws[8];
    __shared__ float snorm;
    if ((tid & 31) == 0) ws[tid >> 5] = s;
    __syncthreads();
    if (tid == 0) {
        float t = 0.f;
        #pragma unroll
        for (int i = 0; i < 8; i++) t += ws[i];
        snorm = rsqrtf(t * (1.0f / DIMC) + EPSV);
    }
    __syncthreads();
    float n = snorm;
    float4 gv = *(const float4*)(g + tid * 4);
    float4 ov;
    ov.x = xv.x * n * gv.x;
    ov.y = xv.y * n * gv.y;
    ov.z = xv.z * n * gv.z;
    ov.w = xv.w * n * gv.w;
    *(float4*)(y + (size_t)row * DIMC + tid * 4) = ov;
}

// ---------------- SGEMM 128x128x8, 8x8 microtile ----------------------------
// C[M,N] = A[M,K] @ B[K,N]  (+ residual) (silu applied before residual/write)
// All of M,N,K are multiples of 128/8 here -> no bounds checks.
__global__ __launch_bounds__(256, 2)
void sgemm_kernel(const float* __restrict__ A, const float* __restrict__ B,
                  float* __restrict__ C, const float* __restrict__ res,
                  int M, int N, int K, int do_silu) {
    __shared__ float As[8][128];
    __shared__ float Bs[8][128];
    int tid = threadIdx.x;                // 256
    int tx  = tid & 15;                   // 0..15 (N dir)
    int ty  = tid >> 4;                   // 0..15 (M dir)
    int bn0 = blockIdx.x * 128;
    int bm0 = blockIdx.y * 128;

    int a_row = tid >> 1;                 // 0..127
    int a_k   = (tid & 1) << 2;           // 0 or 4
    int b_k   = tid >> 5;                 // 0..7
    int b_n   = (tid & 31) << 2;          // 0..124

    const float* Ap = A + (size_t)(bm0 + a_row) * K + a_k;
    const float* Bp = B + (size_t)b_k * N + bn0 + b_n;

    float acc[8][8];
    #pragma unroll
    for (int i = 0; i < 8; i++)
        #pragma unroll
        for (int j = 0; j < 8; j++) acc[i][j] = 0.f;

    for (int k0 = 0; k0 < K; k0 += 8) {
        float4 av = *(const float4*)(Ap + k0);
        float4 bv = *(const float4*)(Bp + (size_t)k0 * N);
        As[a_k + 0][a_row] = av.x;
        As[a_k + 1][a_row] = av.y;
        As[a_k + 2][a_row] = av.z;
        As[a_k + 3][a_row] = av.w;
        *(float4*)&Bs[b_k][b_n] = bv;
        __syncthreads();
        #pragma unroll
        for (int kk = 0; kk < 8; kk++) {
            float ar[8], br[8];
            *(float4*)&ar[0] = *(const float4*)&As[kk][ty * 4];
            *(float4*)&ar[4] = *(const float4*)&As[kk][ty * 4 + 64];
            *(float4*)&br[0] = *(const float4*)&Bs[kk][tx * 4];
            *(float4*)&br[4] = *(const float4*)&Bs[kk][tx * 4 + 64];
            #pragma unroll
            for (int i = 0; i < 8; i++)
                #pragma unroll
                for (int j = 0; j < 8; j++)
                    acc[i][j] += ar[i] * br[j];
        }
        __syncthreads();
    }

    // epilogue
    #pragma unroll
    for (int i = 0; i < 8; i++) {
        int r = bm0 + ty * 4 + ((i < 4) ? i : (60 + i));   // i>=4 -> +64+(i-4)
        #pragma unroll
        for (int jh = 0; jh < 2; jh++) {
            int c = bn0 + tx * 4 + jh * 64;
            float v0 = acc[i][jh * 4 + 0];
            float v1 = acc[i][jh * 4 + 1];
            float v2 = acc[i][jh * 4 + 2];
            float v3 = acc[i][jh * 4 + 3];
            if (do_silu) {
                v0 = v0 / (1.f + __expf(-v0));
                v1 = v1 / (1.f + __expf(-v1));
                v2 = v2 / (1.f + __expf(-v2));
                v3 = v3 / (1.f + __expf(-v3));
            }
            if (res) {
                float4 rv = *(const float4*)(res + (size_t)r * N + c);
                v0 += rv.x; v1 += rv.y; v2 += rv.z; v3 += rv.w;
            }
            float4 ov = make_float4(v0, v1, v2, v3);
            *(float4*)(C + (size_t)r * N + c) = ov;
        }
    }
}

// ---------------- Flash attention (causal, HD=64) ---------------------------
// grid: (B*NH, T/64). Block = 256 threads.
// Q/K/V layout: [B*T, DIM] with head h at columns h*64..h*64+63.
#define ATT_BM  64
#define ATT_ST  68                       // row stride in floats (pad for banks)
#define ATT_SMEM ((4 * 64 * ATT_ST + 3 * 64) * 4)

__global__ void attn_kernel(const float* __restrict__ Q,
                            const float* __restrict__ K,
                            const float* __restrict__ V,
                            float* __restrict__ O) {
    extern __shared__ float sm[];
    float* Qs   = sm;
    float* Ks   = Qs + 64 * ATT_ST;
    float* Vs   = Ks + 64 * ATT_ST;
    float* Ss   = Vs + 64 * ATT_ST;
    float* mrow = Ss + 64 * ATT_ST;
    float* lrow = mrow + 64;
    float* arow = lrow + 64;

    int bh = blockIdx.x;                 // 0..31
    int qt = blockIdx.y;                 // 0..31
    int b  = bh >> 4, h = bh & 15;
    int tid = threadIdx.x;
    int q0 = qt * 64;

    const float* Qb = Q + (size_t)(b * TT) * DIMC + h * HD;
    const float* Kb = K + (size_t)(b * TT) * DIMC + h * HD;
    const float* Vb = V + (size_t)(b * TT) * DIMC + h * HD;

    // load Q tile (64x64), float4
    for (int i = tid; i < 64 * 16; i += 256) {
        int r = i >> 4, c4 = (i & 15) << 2;
        *(float4*)&Qs[r * ATT_ST + c4] =
            *(const float4*)(Qb + (size_t)(q0 + r) * DIMC + c4);
    }
    if (tid < 64) { mrow[tid] = -3.0e38f; lrow[tid] = 0.f; }

    float o[16];
    #pragma unroll
    for (int c = 0; c < 16; c++) o[c] = 0.f;
    int orow = tid >> 2;                 // 0..63
    int od0  = (tid & 3) << 4;           // 0,16,32,48
    int ty = tid >> 4, tx = tid & 15;
    __syncthreads();

    int nkt = qt + 1;
    for (int kt = 0; kt < nkt; kt++) {
        int k0 = kt * 64;
        // load K,V tiles
        for (int i = tid; i < 64 * 16; i += 256) {
            int r = i >> 4, c4 = (i & 15) << 2;
            *(float4*)&Ks[r * ATT_ST + c4] =
                *(const float4*)(Kb + (size_t)(k0 + r) * DIMC + c4);
            *(float4*)&Vs[r * ATT_ST + c4] =
                *(const float4*)(Vb + (size_t)(k0 + r) * DIMC + c4);
        }
        __syncthreads();

        // S = Q K^T / 8 ; thread -> rows ty*4+ii, cols jj*16+tx
        float sacc[4][4];
        #pragma unroll
        for (int ii = 0; ii < 4; ii++)
            #pragma unroll
            for (int jj = 0; jj < 4; jj++) sacc[ii][jj] = 0.f;
        for (int d = 0; d < 64; d += 4) {
            float4 aa[4], bb[4];
            #pragma unroll
            for (int ii = 0; ii < 4; ii++)
                aa[ii] = *(const float4*)&Qs[(ty * 4 + ii) * ATT_ST + d];
            #pragma unroll
            for (int jj = 0; jj < 4; jj++)
                bb[jj] = *(const float4*)&Ks[(jj * 16 + tx) * ATT_ST + d];
            #pragma unroll
            for (int ii = 0; ii < 4; ii++) {
                #pragma unroll
                for (int jj = 0; jj < 4; jj++) {
                    sacc[ii][jj] += aa[ii].x * bb[jj].x;
                    sacc[ii][jj] += aa[ii].y * bb[jj].y;
                    sacc[ii][jj] += aa[ii].z * bb[jj].z;
                    sacc[ii][jj] += aa[ii].w * bb[jj].w;
                }
            }
        }
        bool diag = (kt == qt);
        #pragma unroll
        for (int ii = 0; ii < 4; ii++) {
            #pragma unroll
            for (int jj = 0; jj < 4; jj++) {
                int i = ty * 4 + ii, j = jj * 16 + tx;
                float s = sacc[ii][jj] * 0.125f;
                if (diag && j > i) s = -3.0e38f;
                Ss[i * ATT_ST + j] = s;
            }
        }
        __syncthreads();

        // online softmax per row (threads 0..63)
        if (tid < 64) {
            int r = tid;
            float m_old = mrow[r];
            float mx = m_old;
            #pragma unroll 8
            for (int j = 0; j < 64; j++) mx = fmaxf(mx, Ss[r * ATT_ST + j]);
            float alpha = __expf(m_old - mx);
            float sum = 0.f;
            #pragma unroll 8
            for (int j = 0; j < 64; j++) {
                float p = __expf(Ss[r * ATT_ST + j] - mx);
                Ss[r * ATT_ST + j] = p;
                sum += p;
            }
            mrow[r] = mx;
            lrow[r] = lrow[r] * alpha + sum;
            arow[r] = alpha;
        }
        __syncthreads();

        // rescale + O += P @ V
        float alpha = arow[orow];
        #pragma unroll
        for (int c = 0; c < 16; c++) o[c] *= alpha;
        #pragma unroll 2
        for (int j = 0; j < 64; j++) {
            float p = Ss[orow * ATT_ST + j];
            const float* vr = &Vs[j * ATT_ST + od0];
            float4 v0 = *(const float4*)(vr + 0);
            float4 v1 = *(const float4*)(vr + 4);
            float4 v2 = *(const float4*)(vr + 8);
            float4 v3 = *(const float4*)(vr + 12);
            o[0]  += p * v0.x; o[1]  += p * v0.y; o[2]  += p * v0.z; o[3]  += p * v0.w;
            o[4]  += p * v1.x; o[5]  += p * v1.y; o[6]  += p * v1.z; o[7]  += p * v1.w;
            o[8]  += p * v2.x; o[9]  += p * v2.y; o[10] += p * v2.z; o[11] += p * v2.w;
            o[12] += p * v3.x; o[13] += p * v3.y; o[14] += p * v3.z; o[15] += p * v3.w;
        }
        __syncthreads();
    }

    float inv_l = 1.0f / lrow[orow];
    float* Ob = O + (size_t)(b * TT + q0 + orow) * DIMC + h * HD + od0;
    #pragma unroll
    for (int c4 = 0; c4 < 4; c4++) {
        float4 ov = make_float4(o[c4*4+0] * inv_l, o[c4*4+1] * inv_l,
                                o[c4*4+2] * inv_l, o[c4*4+3] * inv_l);
        *(float4*)(Ob + c4 * 4) = ov;
    }
}

// ---------------- launcher --------------------------------------------------
extern "C" void kernel_launch(void* const* d_in, const int* in_sizes, int n_in,
                              void* d_out, int out_size) {
    const float* x  = (const float*)d_in[0];
    // d_in[1] = mask (causal; implemented implicitly)
    const float* wq = (const float*)d_in[2];
    const float* wk = (const float*)d_in[3];
    const float* wv = (const float*)d_in[4];
    const float* wo = (const float*)d_in[5];
    const float* w1 = (const float*)d_in[6];
    const float* w2 = (const float*)d_in[7];
    const float* ga = (const float*)d_in[8];
    const float* gf = (const float*)d_in[9];
    float* out = (float*)d_out;

    float *xn, *q, *k, *v, *ao, *x1, *hb;
    cudaGetSymbolAddress((void**)&xn, g_xn);
    cudaGetSymbolAddress((void**)&q,  g_q);
    cudaGetSymbolAddress((void**)&k,  g_k);
    cudaGetSymbolAddress((void**)&v,  g_v);
    cudaGetSymbolAddress((void**)&ao, g_ao);
    cudaGetSymbolAddress((void**)&x1, g_x1);
    cudaGetSymbolAddress((void**)&hb, g_h);

    cudaFuncSetAttribute(attn_kernel,
                         cudaFuncAttributeMaxDynamicSharedMemorySize, ATT_SMEM);

    dim3 gN1(DIMC / 128, BT / 128);   // (8, 32)
    dim3 gN4(HID  / 128, BT / 128);   // (32, 32)

    // 1) xn = rmsnorm(x, g_attn)
    rmsnorm_kernel<<<BT, 256>>>(x, ga, xn);
    // 2) q,k,v projections
    sgemm_kernel<<<gN1, 256>>>(xn, wq, q, nullptr, BT, DIMC, DIMC, 0);
    sgemm_kernel<<<gN1, 256>>>(xn, wk, k, nullptr, BT, DIMC, DIMC, 0);
    sgemm_kernel<<<gN1, 256>>>(xn, wv, v, nullptr, BT, DIMC, DIMC, 0);
    // 3) attention
    attn_kernel<<<dim3(BB * NH, TT / 64), 256, ATT_SMEM>>>(q, k, v, ao);
    // 4) x1 = x + ao @ wo
    sgemm_kernel<<<gN1, 256>>>(ao, wo, x1, x, BT, DIMC, DIMC, 0);
    // 5) xn = rmsnorm(x1, g_ffn)
    rmsnorm_kernel<<<BT, 256>>>(x1, gf, xn);
    // 6) hb = silu(xn @ w1)
    sgemm_kernel<<<gN4, 256>>>(xn, w1, hb, nullptr, BT, HID, DIMC, 1);
    // 7) out = x1 + hb @ w2
    sgemm_kernel<<<gN1, 256>>>(hb, w2, out, x1, BT, DIMC, HID, 0);
}

// round 2
// speedup vs baseline: 3.7018x; 3.7018x over previous
#include <cuda_runtime.h>
#include <math.h>

// Problem constants
#define BB   2
#define TT   2048
#define BT   4096
#define DIMC 1024
#define NH   16
#define HD   64
#define HID  4096
#define EPSV 1e-6f

// ---------------- scratch ----------------------------------------------------
__device__ float g_xn[BT * DIMC];
__device__ float g_q [BT * DIMC];
__device__ float g_k [BT * DIMC];
__device__ float g_v [BT * DIMC];
__device__ float g_ao[BT * DIMC];
__device__ float g_x1[BT * DIMC];
__device__ float g_h [BT * HID];

// ---------------- tf32 helpers -----------------------------------------------
__device__ __forceinline__ unsigned f2tf(float f) {
    unsigned u;
    asm("cvt.rna.tf32.f32 %0, %1;" : "=r"(u) : "f"(f));
    return u;
}

__device__ __forceinline__ void mma8(float* d, const unsigned* a, const unsigned* b) {
    asm volatile(
        "mma.sync.aligned.m16n8k8.row.col.f32.tf32.tf32.f32 "
        "{%0,%1,%2,%3}, {%4,%5,%6,%7}, {%8,%9}, {%0,%1,%2,%3};"
        : "+f"(d[0]), "+f"(d[1]), "+f"(d[2]), "+f"(d[3])
        : "r"(a[0]), "r"(a[1]), "r"(a[2]), "r"(a[3]), "r"(b[0]), "r"(b[1]));
}

// ---------------- RMSNorm ----------------------------------------------------
__global__ void rmsnorm_kernel(const float* __restrict__ x,
                               const float* __restrict__ g,
                               float* __restrict__ y) {
    int row = blockIdx.x;
    int tid = threadIdx.x;
    const float* xr = x + (size_t)row * DIMC;
    float4 xv = *(const float4*)(xr + tid * 4);
    float s = xv.x * xv.x + xv.y * xv.y + xv.z * xv.z + xv.w * xv.w;
    #pragma unroll
    for (int off = 16; off; off >>= 1) s += __shfl_xor_sync(0xFFFFFFFFu, s, off);
    __shared__ float ws[8];
    __shared__ float snorm;
    if ((tid & 31) == 0) ws[tid >> 5] = s;
    __syncthreads();
    if (tid == 0) {
        float t = 0.f;
        #pragma unroll
        for (int i = 0; i < 8; i++) t += ws[i];
        snorm = rsqrtf(t * (1.0f / DIMC) + EPSV);
    }
    __syncthreads();
    float n = snorm;
    float4 gv = *(const float4*)(g + tid * 4);
    float4 ov;
    ov.x = xv.x * n * gv.x;
    ov.y = xv.y * n * gv.y;
    ov.z = xv.z * n * gv.z;
    ov.w = xv.w * n * gv.w;
    *(float4*)(y + (size_t)row * DIMC + tid * 4) = ov;
}

// ---------------- TF32 GEMM 128x128, K-tile 32 --------------------------------
// 256 threads = 8 warps in 2(M) x 4(N); warp tile 64x32 as 4x4 m16n8k8 tiles.
#define LDAS 36
#define LDBS 132

__global__ __launch_bounds__(256, 2)
void gemm_tf32(const float* __restrict__ A, const float* __restrict__ B,
               float* __restrict__ C, const float* __restrict__ res,
               int M, int N, int K, int do_silu) {
    __shared__ unsigned As[128 * LDAS];   // [row][k]
    __shared__ unsigned Bs[32 * LDBS];    // [k][col]

    int tid  = threadIdx.x;
    int warp = tid >> 5, lane = tid & 31;
    int g = lane >> 2, tg = lane & 3;
    int wm = warp >> 2, wn = warp & 3;
    int bm0 = blockIdx.y * 128, bn0 = blockIdx.x * 128;

    float acc[4][4][4];
    #pragma unroll
    for (int mt = 0; mt < 4; mt++)
        #pragma unroll
        for (int nt = 0; nt < 4; nt++)
            #pragma unroll
            for (int r = 0; r < 4; r++) acc[mt][nt][r] = 0.f;

    int ar = tid >> 3, ac = (tid & 7) * 4;   // A loader: rows ar+32i, cols ac..ac+3
    int br = tid >> 5, bc = (tid & 31) * 4;  // B loader: rows br+8i,  cols bc..bc+3
    const float* Ap = A + (size_t)(bm0 + ar) * K + ac;
    const float* Bp = B + (size_t)br * N + bn0 + bc;

    for (int k0 = 0; k0 < K; k0 += 32) {
        #pragma unroll
        for (int i = 0; i < 4; i++) {
            float4 v = *(const float4*)(Ap + (size_t)i * 32 * K + k0);
            unsigned* d = &As[(ar + i * 32) * LDAS + ac];
            d[0] = f2tf(v.x); d[1] = f2tf(v.y); d[2] = f2tf(v.z); d[3] = f2tf(v.w);
        }
        #pragma unroll
        for (int i = 0; i < 4; i++) {
            float4 v = *(const float4*)(Bp + (size_t)(k0 + i * 8) * N);
            unsigned* d = &Bs[(br + i * 8) * LDBS + bc];
            d[0] = f2tf(v.x); d[1] = f2tf(v.y); d[2] = f2tf(v.z); d[3] = f2tf(v.w);
        }
        __syncthreads();

        #pragma unroll
        for (int kk = 0; kk < 4; kk++) {
            unsigned a[4][4], b[4][2];
            #pragma unroll
            for (int mt = 0; mt < 4; mt++) {
                const unsigned* p = &As[(wm * 64 + mt * 16 + g) * LDAS + kk * 8 + tg];
                a[mt][0] = p[0];
                a[mt][1] = p[8 * LDAS];
                a[mt][2] = p[4];
                a[mt][3] = p[8 * LDAS + 4];
            }
            #pragma unroll
            for (int nt = 0; nt < 4; nt++) {
                const unsigned* p = &Bs[(kk * 8 + tg) * LDBS + wn * 32 + nt * 8 + g];
                b[nt][0] = p[0];
                b[nt][1] = p[4 * LDBS];
            }
            #pragma unroll
            for (int mt = 0; mt < 4; mt++)
                #pragma unroll
                for (int nt = 0; nt < 4; nt++)
                    mma8(acc[mt][nt], a[mt], b[nt]);
        }
        __syncthreads();
    }

    // epilogue: rows wm*64+mt*16+g(+8), cols wn*32+nt*8+2tg(+1)
    #pragma unroll
    for (int mt = 0; mt < 4; mt++) {
        #pragma unroll
        for (int half = 0; half < 2; half++) {
            int r = bm0 + wm * 64 + mt * 16 + g + half * 8;
            #pragma unroll
            for (int nt = 0; nt < 4; nt++) {
                int c = bn0 + wn * 32 + nt * 8 + 2 * tg;
                float v0 = acc[mt][nt][half * 2 + 0];
                float v1 = acc[mt][nt][half * 2 + 1];
                if (do_silu) {
                    v0 = v0 / (1.f + __expf(-v0));
                    v1 = v1 / (1.f + __expf(-v1));
                }
                if (res) {
                    float2 rv = *(const float2*)(res + (size_t)r * N + c);
                    v0 += rv.x; v1 += rv.y;
                }
                *(float2*)(C + (size_t)r * N + c) = make_float2(v0, v1);
            }
        }
    }
}

// ---------------- Flash attention, tf32 tensor-core --------------------------
// grid (B*NH, T/64), 128 threads (4 warps). Warp owns 16 Q rows.
#define AST 68
#define ATT_SMEM (3 * 64 * AST * 4)

__global__ void attn_tf32(const float* __restrict__ Q, const float* __restrict__ K,
                          const float* __restrict__ V, float* __restrict__ O) {
    extern __shared__ unsigned smu[];
    unsigned* Ks = smu;                 // [64][AST]
    unsigned* Vs = Ks + 64 * AST;
    unsigned* Ps = Vs + 64 * AST;

    int bh = blockIdx.x, qt = blockIdx.y;
    int b = bh >> 4, h = bh & 15;
    int q0 = qt * 64;
    int tid = threadIdx.x, warp = tid >> 5, lane = tid & 31;
    int g = lane >> 2, tg = lane & 3;
    int r0l = warp * 16 + g;            // local Q row (and +8)

    const float* Qb = Q + ((size_t)(b * TT + q0)) * DIMC + h * HD;
    const float* Kb = K + ((size_t)(b * TT)) * DIMC + h * HD;
    const float* Vb = V + ((size_t)(b * TT)) * DIMC + h * HD;

    // Q as A-fragments, pre-scaled by 1/sqrt(64)
    unsigned qa[8][4];
    #pragma unroll
    for (int kt = 0; kt < 8; kt++) {
        qa[kt][0] = f2tf(Qb[(size_t)r0l * DIMC + kt * 8 + tg] * 0.125f);
        qa[kt][1] = f2tf(Qb[(size_t)(r0l + 8) * DIMC + kt * 8 + tg] * 0.125f);
        qa[kt][2] = f2tf(Qb[(size_t)r0l * DIMC + kt * 8 + tg + 4] * 0.125f);
        qa[kt][3] = f2tf(Qb[(size_t)(r0l + 8) * DIMC + kt * 8 + tg + 4] * 0.125f);
    }

    float oacc[8][4];
    #pragma unroll
    for (int nt = 0; nt < 8; nt++)
        #pragma unroll
        for (int r = 0; r < 4; r++) oacc[nt][r] = 0.f;
    float m0 = -1e30f, m1 = -1e30f, l0 = 0.f, l1 = 0.f;
    int r0g = q0 + r0l, r1g = r0g + 8;

    for (int s0 = 0; s0 <= q0; s0 += 64) {
        // load + convert K,V tiles
        for (int i = tid; i < 1024; i += 128) {
            int r = i >> 4, c = (i & 15) << 2;
            float4 kv = *(const float4*)(Kb + (size_t)(s0 + r) * DIMC + c);
            unsigned* d = &Ks[r * AST + c];
            d[0] = f2tf(kv.x); d[1] = f2tf(kv.y); d[2] = f2tf(kv.z); d[3] = f2tf(kv.w);
            float4 vv = *(const float4*)(Vb + (size_t)(s0 + r) * DIMC + c);
            unsigned* e = &Vs[r * AST + c];
            e[0] = f2tf(vv.x); e[1] = f2tf(vv.y); e[2] = f2tf(vv.z); e[3] = f2tf(vv.w);
        }
        __syncthreads();

        // S = Q K^T
        float sc[8][4];
        #pragma unroll
        for (int nt = 0; nt < 8; nt++)
            #pragma unroll
            for (int r = 0; r < 4; r++) sc[nt][r] = 0.f;
        #pragma unroll
        for (int kk = 0; kk < 8; kk++) {
            #pragma unroll
            for (int nt = 0; nt < 8; nt++) {
                unsigned bf[2];
                const unsigned* p = &Ks[(nt * 8 + g) * AST + kk * 8 + tg];
                bf[0] = p[0];
                bf[1] = p[4];
                mma8(sc[nt], qa[kk], bf);
            }
        }

        // causal mask (only diagonal tile)
        if (s0 == q0) {
            #pragma unroll
            for (int nt = 0; nt < 8; nt++) {
                int j = s0 + nt * 8 + 2 * tg;
                if (j     > r0g) sc[nt][0] = -1e30f;
                if (j + 1 > r0g) sc[nt][1] = -1e30f;
                if (j     > r1g) sc[nt][2] = -1e30f;
                if (j + 1 > r1g) sc[nt][3] = -1e30f;
            }
        }

        // online softmax (registers + quad shuffles)
        float mx0 = -1e30f, mx1 = -1e30f;
        #pragma unroll
        for (int nt = 0; nt < 8; nt++) {
            mx0 = fmaxf(mx0, fmaxf(sc[nt][0], sc[nt][1]));
            mx1 = fmaxf(mx1, fmaxf(sc[nt][2], sc[nt][3]));
        }
        mx0 = fmaxf(mx0, __shfl_xor_sync(0xFFFFFFFFu, mx0, 1));
        mx0 = fmaxf(mx0, __shfl_xor_sync(0xFFFFFFFFu, mx0, 2));
        mx1 = fmaxf(mx1, __shfl_xor_sync(0xFFFFFFFFu, mx1, 1));
        mx1 = fmaxf(mx1, __shfl_xor_sync(0xFFFFFFFFu, mx1, 2));
        float mn0 = fmaxf(m0, mx0), mn1 = fmaxf(m1, mx1);
        float al0 = __expf(m0 - mn0), al1 = __expf(m1 - mn1);
        float s0r = 0.f, s1r = 0.f;
        #pragma unroll
        for (int nt = 0; nt < 8; nt++) {
            sc[nt][0] = __expf(sc[nt][0] - mn0);
            sc[nt][1] = __expf(sc[nt][1] - mn0);
            sc[nt][2] = __expf(sc[nt][2] - mn1);
            sc[nt][3] = __expf(sc[nt][3] - mn1);
            s0r += sc[nt][0] + sc[nt][1];
            s1r += sc[nt][2] + sc[nt][3];
        }
        s0r += __shfl_xor_sync(0xFFFFFFFFu, s0r, 1);
        s0r += __shfl_xor_sync(0xFFFFFFFFu, s0r, 2);
        s1r += __shfl_xor_sync(0xFFFFFFFFu, s1r, 1);
        s1r += __shfl_xor_sync(0xFFFFFFFFu, s1r, 2);
        l0 = l0 * al0 + s0r;
        l1 = l1 * al1 + s1r;
        m0 = mn0; m1 = mn1;
        #pragma unroll
        for (int nt = 0; nt < 8; nt++) {
            oacc[nt][0] *= al0; oacc[nt][1] *= al0;
            oacc[nt][2] *= al1; oacc[nt][3] *= al1;
        }

        // P -> smem (own warp region), re-read as A-fragments
        #pragma unroll
        for (int nt = 0; nt < 8; nt++) {
            Ps[r0l * AST + nt * 8 + 2 * tg]           = f2tf(sc[nt][0]);
            Ps[r0l * AST + nt * 8 + 2 * tg + 1]       = f2tf(sc[nt][1]);
            Ps[(r0l + 8) * AST + nt * 8 + 2 * tg]     = f2tf(sc[nt][2]);
            Ps[(r0l + 8) * AST + nt * 8 + 2 * tg + 1] = f2tf(sc[nt][3]);
        }
        __syncwarp();
        unsigned pa[8][4];
        #pragma unroll
        for (int kt = 0; kt < 8; kt++) {
            const unsigned* p = &Ps[r0l * AST + kt * 8 + tg];
            pa[kt][0] = p[0];
            pa[kt][1] = p[8 * AST];
            pa[kt][2] = p[4];
            pa[kt][3] = p[8 * AST + 4];
        }

        // O += P @ V
        #pragma unroll
        for (int kt = 0; kt < 8; kt++) {
            #pragma unroll
            for (int nt = 0; nt < 8; nt++) {
                unsigned bf[2];
                bf[0] = Vs[(kt * 8 + tg) * AST + nt * 8 + g];
                bf[1] = Vs[(kt * 8 + tg + 4) * AST + nt * 8 + g];
                mma8(oacc[nt], pa[kt], bf);
            }
        }
        __syncthreads();
    }

    float il0 = 1.f / l0, il1 = 1.f / l1;
    float* Ob = O + ((size_t)(b * TT + q0 + r0l)) * DIMC + h * HD;
    #pragma unroll
    for (int nt = 0; nt < 8; nt++) {
        *(float2*)(Ob + nt * 8 + 2 * tg) =
            make_float2(oacc[nt][0] * il0, oacc[nt][1] * il0);
        *(float2*)(Ob + (size_t)8 * DIMC + nt * 8 + 2 * tg) =
            make_float2(oacc[nt][2] * il1, oacc[nt][3] * il1);
    }
}

// ---------------- launcher ----------------------------------------------------
extern "C" void kernel_launch(void* const* d_in, const int* in_sizes, int n_in,
                              void* d_out, int out_size) {
    const float* x  = (const float*)d_in[0];
    const float* wq = (const float*)d_in[2];
    const float* wk = (const float*)d_in[3];
    const float* wv = (const float*)d_in[4];
    const float* wo = (const float*)d_in[5];
    const float* w1 = (const float*)d_in[6];
    const float* w2 = (const float*)d_in[7];
    const float* ga = (const float*)d_in[8];
    const float* gf = (const float*)d_in[9];
    float* out = (float*)d_out;

    float *xn, *q, *k, *v, *ao, *x1, *hb;
    cudaGetSymbolAddress((void**)&xn, g_xn);
    cudaGetSymbolAddress((void**)&q,  g_q);
    cudaGetSymbolAddress((void**)&k,  g_k);
    cudaGetSymbolAddress((void**)&v,  g_v);
    cudaGetSymbolAddress((void**)&ao, g_ao);
    cudaGetSymbolAddress((void**)&x1, g_x1);
    cudaGetSymbolAddress((void**)&hb, g_h);

    cudaFuncSetAttribute(attn_tf32,
                         cudaFuncAttributeMaxDynamicSharedMemorySize, ATT_SMEM);

    dim3 gN1(DIMC / 128, BT / 128);   // (8, 32)
    dim3 gN4(HID  / 128, BT / 128);   // (32, 32)

    rmsnorm_kernel<<<BT, 256>>>(x, ga, xn);
    gemm_tf32<<<gN1, 256>>>(xn, wq, q, nullptr, BT, DIMC, DIMC, 0);
    gemm_tf32<<<gN1, 256>>>(xn, wk, k, nullptr, BT, DIMC, DIMC, 0);
    gemm_tf32<<<gN1, 256>>>(xn, wv, v, nullptr, BT, DIMC, DIMC, 0);
    attn_tf32<<<dim3(BB * NH, TT / 64), 128, ATT_SMEM>>>(q, k, v, ao);
    gemm_tf32<<<gN1, 256>>>(ao, wo, x1, x, BT, DIMC, DIMC, 0);
    rmsnorm_kernel<<<BT, 256>>>(x1, gf, xn);
    gemm_tf32<<<gN4, 256>>>(xn, w1, hb, nullptr, BT, HID, DIMC, 1);
    gemm_tf32<<<gN1, 256>>>(hb, w2, out, x1, BT, DIMC, HID, 0);
}